// round 1
// baseline (speedup 1.0000x reference)
#include <cuda_runtime.h>
#include <math.h>

#define NTOK 1024
#define DIMV 512
#define HIDV 2048
#define NEXP 64

// ---------------- scratch (device globals; no allocation allowed) ----------
__device__ float g_h[NTOK * HIDV];     // hidden activations after GELU (8 MB)
__device__ int   g_idx[2][NTOK];
__device__ float g_gate[2][NTOK];
__device__ int   g_cnt[2][NEXP];
__device__ int   g_off[2][NEXP];
__device__ int   g_list[2][NTOK];

// ---------------- packed f32x2 FMA (Blackwell) ------------------------------
__device__ __forceinline__ float2 ffma2(float2 a, float2 b, float2 c) {
    float2 d;
    asm("fma.rn.f32x2 %0, %1, %2, %3;"
        : "=l"(*reinterpret_cast<unsigned long long*>(&d))
        : "l"(*reinterpret_cast<const unsigned long long*>(&a)),
          "l"(*reinterpret_cast<const unsigned long long*>(&b)),
          "l"(*reinterpret_cast<const unsigned long long*>(&c)));
    return d;
}

__device__ __forceinline__ float gelu_f(float v) {
    return 0.5f * v * (1.0f + erff(v * 0.70710678118654752440f));
}

// ---------------- reset per-launch counters ---------------------------------
__global__ void zero_kernel() {
    int t = threadIdx.x;
    if (t < NEXP) { g_cnt[0][t] = 0; g_cnt[1][t] = 0; }
}

// ---------------- top-1 gating: softmax max prob + argmax -------------------
// grid = NTOK blocks, 64 threads (one expert per thread)
__global__ void gating_kernel(const float* __restrict__ X,
                              const float* __restrict__ EMB,
                              int din, float scale, int layer) {
    __shared__ float s_x[HIDV];
    __shared__ float s_logit[NEXP];
    const int token = blockIdx.x;
    const float4* xr4 = (const float4*)(X + (size_t)token * din);
    float4* sx4 = (float4*)s_x;
    const int d4 = din >> 2;
    for (int i = threadIdx.x; i < d4; i += 64) sx4[i] = xr4[i];
    __syncthreads();

    const int e = threadIdx.x;  // 0..63
    const float4* er4 = (const float4*)(EMB + (size_t)e * din);
    float a0 = 0.f, a1 = 0.f, a2 = 0.f, a3 = 0.f;
    for (int i = 0; i < d4; i++) {
        float4 w = er4[i];
        float4 x = sx4[i];
        a0 += x.x * w.x; a1 += x.y * w.y; a2 += x.z * w.z; a3 += x.w * w.w;
    }
    s_logit[e] = ((a0 + a1) + (a2 + a3)) * scale;
    __syncthreads();

    if (threadIdx.x == 0) {
        float m = s_logit[0]; int mi = 0;
        for (int i = 1; i < NEXP; i++)
            if (s_logit[i] > m) { m = s_logit[i]; mi = i; }
        float s = 0.f;
        for (int i = 0; i < NEXP; i++) s += expf(s_logit[i] - m);
        g_idx[layer][token]  = mi;
        g_gate[layer][token] = 1.0f / s;   // max softmax prob
        atomicAdd(&g_cnt[layer][mi], 1);
    }
}

// ---------------- build per-expert token lists ------------------------------
__global__ void group_kernel(int layer) {
    __shared__ int s_cur[NEXP];
    if (threadIdx.x == 0) {
        int a = 0;
        for (int e = 0; e < NEXP; e++) {
            g_off[layer][e] = a;
            s_cur[e] = a;
            a += g_cnt[layer][e];
        }
    }
    __syncthreads();
    for (int i = threadIdx.x; i < NTOK; i += blockDim.x) {
        int e = g_idx[layer][i];
        int p = atomicAdd(&s_cur[e], 1);
        g_list[layer][p] = i;
    }
}

// ---------------- grouped expert FC ------------------------------------------
// grid = (DOUT / (32*CPT), NEXP); 128 threads.
// Warp w handles tokens 4w..4w+3 of the current 16-token chunk;
// lane l handles CPT consecutive output columns.
template<int DIN, int DOUT, int CPT, bool GELU>
__global__ void fc_kernel(const float* __restrict__ X,
                          const float* __restrict__ W,
                          const float* __restrict__ Bv,
                          int layer,
                          float* __restrict__ OUT) {
    constexpr int COLS = 32 * CPT;
    constexpr int NP = CPT / 2;
    const int e = blockIdx.y;
    const int m = g_cnt[layer][e];
    if (m == 0) return;

    const int lane = threadIdx.x & 31;
    const int wg = threadIdx.x >> 5;                 // warp id 0..3
    const int colBase = blockIdx.x * COLS + lane * CPT;

    __shared__ float s_x[16][512];
    __shared__ int s_row[16];

    const int base = g_off[layer][e];
    const float* Wb = W + (size_t)e * DIN * DOUT + colBase;
    const float* gatep = g_gate[layer];

    float bl[CPT];
    {
        const float* bp = Bv + (size_t)e * DOUT + colBase;
        #pragma unroll
        for (int c = 0; c < CPT; c++) bl[c] = bp[c];
    }

    for (int t0 = 0; t0 < m; t0 += 16) {
        __syncthreads();   // protect s_row/s_x from previous iteration's readers
        if (threadIdx.x < 16)
            s_row[threadIdx.x] = (t0 + threadIdx.x < m)
                                 ? g_list[layer][base + t0 + threadIdx.x] : -1;

        float2 acc[4][NP];
        #pragma unroll
        for (int j = 0; j < 4; j++)
            #pragma unroll
            for (int p = 0; p < NP; p++) acc[j][p] = make_float2(0.f, 0.f);

        for (int kc = 0; kc < DIN; kc += 512) {
            __syncthreads();
            // stage 16 x 512 chunk of X (float4, coalesced)
            for (int i = threadIdx.x; i < 16 * 128; i += 128) {
                int t = i >> 7, k4 = i & 127;
                int r = s_row[t];
                float4 v = (r >= 0)
                    ? *(const float4*)(X + (size_t)r * DIN + kc + k4 * 4)
                    : make_float4(0.f, 0.f, 0.f, 0.f);
                *(float4*)&s_x[t][k4 * 4] = v;
            }
            __syncthreads();

            const float* wp = Wb + (size_t)kc * DOUT;
            #pragma unroll 4
            for (int k = 0; k < 512; k++) {
                float2 wv[NP];
                if constexpr (CPT == 4) {
                    float4 w4 = *(const float4*)wp;
                    wv[0] = make_float2(w4.x, w4.y);
                    wv[1] = make_float2(w4.z, w4.w);
                } else {
                    wv[0] = *(const float2*)wp;
                }
                wp += DOUT;
                #pragma unroll
                for (int j = 0; j < 4; j++) {
                    float xv = s_x[wg * 4 + j][k];   // warp-broadcast LDS
                    float2 xx = make_float2(xv, xv);
                    #pragma unroll
                    for (int p = 0; p < NP; p++)
                        acc[j][p] = ffma2(xx, wv[p], acc[j][p]);
                }
            }
        }

        // epilogue: bias, gate, (gelu), store
        #pragma unroll
        for (int j = 0; j < 4; j++) {
            int r = s_row[wg * 4 + j];
            if (r < 0) continue;
            float g = gatep[r];
            float ov[CPT];
            #pragma unroll
            for (int p = 0; p < NP; p++) {
                float v0 = (acc[j][p].x + bl[2 * p])     * g;
                float v1 = (acc[j][p].y + bl[2 * p + 1]) * g;
                if (GELU) { v0 = gelu_f(v0); v1 = gelu_f(v1); }
                ov[2 * p] = v0; ov[2 * p + 1] = v1;
            }
            float* op = OUT + (size_t)r * DOUT + colBase;
            if constexpr (CPT == 4)
                *(float4*)op = make_float4(ov[0], ov[1], ov[2], ov[3]);
            else
                *(float2*)op = make_float2(ov[0], ov[1]);
        }
    }
}

// ---------------- launch ------------------------------------------------------
extern "C" void kernel_launch(void* const* d_in, const int* in_sizes, int n_in,
                              void* d_out, int out_size) {
    const float* x    = (const float*)d_in[0];
    const float* emb1 = (const float*)d_in[1];
    const float* W1   = (const float*)d_in[2];
    const float* b1   = (const float*)d_in[3];
    const float* emb2 = (const float*)d_in[4];
    const float* W2   = (const float*)d_in[5];
    const float* b2   = (const float*)d_in[6];
    float* out = (float*)d_out;

    void* hp = nullptr;
    cudaGetSymbolAddress(&hp, g_h);
    float* h = (float*)hp;

    const float scale1 = 0.044194173824159216f;   // 1/sqrt(512)
    const float scale2 = 0.022097086912079612f;   // 1/sqrt(2048)

    zero_kernel<<<1, 64>>>();

    gating_kernel<<<NTOK, 64>>>(x, emb1, DIMV, scale1, 0);
    group_kernel<<<1, 256>>>(0);
    fc_kernel<DIMV, HIDV, 4, true><<<dim3(HIDV / 128, NEXP), 128>>>(x, W1, b1, 0, h);

    gating_kernel<<<NTOK, 64>>>(h, emb2, HIDV, scale2, 1);
    group_kernel<<<1, 256>>>(1);
    fc_kernel<HIDV, DIMV, 2, false><<<dim3(DIMV / 64, NEXP), 128>>>(h, W2, b2, 1, out);
}

// round 2
// speedup vs baseline: 2.1302x; 2.1302x over previous
#include <cuda_runtime.h>
#include <math.h>

#define NTOK 1024
#define DIMV 512
#define HIDV 2048
#define NEXP 64

// ---------------- scratch (device globals; no allocation allowed) ----------
__device__ float g_h[NTOK * HIDV];        // hidden activations after GELU (8 MB)
__device__ float g_part[2 * NTOK * DIMV]; // FC2 K-split partials (4 MB)
__device__ int   g_idx[2][NTOK];
__device__ float g_gate[2][NTOK];
__device__ int   g_cnt[2][NEXP];
__device__ int   g_off[2][NEXP];
__device__ int   g_list[2][NTOK];

// ---------------- packed f32x2 FMA (Blackwell) ------------------------------
__device__ __forceinline__ float2 ffma2(float2 a, float2 b, float2 c) {
    float2 d;
    asm("fma.rn.f32x2 %0, %1, %2, %3;"
        : "=l"(*reinterpret_cast<unsigned long long*>(&d))
        : "l"(*reinterpret_cast<const unsigned long long*>(&a)),
          "l"(*reinterpret_cast<const unsigned long long*>(&b)),
          "l"(*reinterpret_cast<const unsigned long long*>(&c)));
    return d;
}

__device__ __forceinline__ float gelu_f(float v) {
    return 0.5f * v * (1.0f + erff(v * 0.70710678118654752440f));
}

// ---------------- reset per-launch counters ---------------------------------
__global__ void zero_kernel() {
    int t = threadIdx.x;
    if (t < NEXP) { g_cnt[0][t] = 0; g_cnt[1][t] = 0; }
}

// ---------------- top-1 gating: softmax max prob + argmax -------------------
// grid = NTOK blocks, 64 threads (one expert per thread)
__global__ void gating_kernel(const float* __restrict__ X,
                              const float* __restrict__ EMB,
                              int din, float scale, int layer) {
    __shared__ float s_x[HIDV];
    __shared__ float s_logit[NEXP];
    const int token = blockIdx.x;
    const float4* xr4 = (const float4*)(X + (size_t)token * din);
    float4* sx4 = (float4*)s_x;
    const int d4 = din >> 2;
    for (int i = threadIdx.x; i < d4; i += 64) sx4[i] = xr4[i];
    __syncthreads();

    const int e = threadIdx.x;  // 0..63
    const float4* er4 = (const float4*)(EMB + (size_t)e * din);
    float a0 = 0.f, a1 = 0.f, a2 = 0.f, a3 = 0.f;
    #pragma unroll 4
    for (int i = 0; i < d4; i++) {
        float4 w = er4[i];
        float4 x = sx4[i];
        a0 += x.x * w.x; a1 += x.y * w.y; a2 += x.z * w.z; a3 += x.w * w.w;
    }
    s_logit[e] = ((a0 + a1) + (a2 + a3)) * scale;
    __syncthreads();

    if (threadIdx.x == 0) {
        float m = s_logit[0]; int mi = 0;
        for (int i = 1; i < NEXP; i++)
            if (s_logit[i] > m) { m = s_logit[i]; mi = i; }
        float s = 0.f;
        for (int i = 0; i < NEXP; i++) s += expf(s_logit[i] - m);
        g_idx[layer][token]  = mi;
        g_gate[layer][token] = 1.0f / s;   // max softmax prob
        atomicAdd(&g_cnt[layer][mi], 1);
    }
}

// ---------------- build per-expert token lists ------------------------------
__global__ void group_kernel(int layer) {
    __shared__ int s_cur[NEXP];
    if (threadIdx.x == 0) {
        int a = 0;
        for (int e = 0; e < NEXP; e++) {
            g_off[layer][e] = a;
            s_cur[e] = a;
            a += g_cnt[layer][e];
        }
    }
    __syncthreads();
    for (int i = threadIdx.x; i < NTOK; i += blockDim.x) {
        int e = g_idx[layer][i];
        int p = atomicAdd(&s_cur[e], 1);
        g_list[layer][p] = i;
    }
}

// ---------------- grouped expert FC ------------------------------------------
// grid = (DOUT/(32*CPT), NEXP, DIN/KLEN); 128 threads.
// Warp w handles tokens 4w..4w+3 of the current 16-token chunk;
// lane l handles CPT consecutive output columns.
// Inner k-loop: 8-deep batched W prefetch (8 independent LDG.128 in flight).
template<int DIN, int DOUT, int CPT, int KLEN, bool GELU, bool EPI>
__global__ void __launch_bounds__(128, 5)
fc_kernel(const float* __restrict__ X,
          const float* __restrict__ W,
          const float* __restrict__ Bv,
          int layer,
          float* __restrict__ OUT) {
    constexpr int COLS = 32 * CPT;
    constexpr int NP = CPT / 2;
    const int e = blockIdx.y;
    const int m = g_cnt[layer][e];
    if (m == 0) return;

    const int lane = threadIdx.x & 31;
    const int wg = threadIdx.x >> 5;                 // warp id 0..3
    const int colBase = blockIdx.x * COLS + lane * CPT;
    const int k0 = blockIdx.z * KLEN;

    __shared__ float s_x[16][512];
    __shared__ int s_row[16];

    const int base = g_off[layer][e];
    const float* Wb = W + (size_t)e * DIN * DOUT + colBase;
    const float* gatep = g_gate[layer];

    float bl[CPT];
    if (EPI) {
        const float* bp = Bv + (size_t)e * DOUT + colBase;
        #pragma unroll
        for (int c = 0; c < CPT; c++) bl[c] = bp[c];
    }

    for (int t0 = 0; t0 < m; t0 += 16) {
        __syncthreads();   // protect s_row/s_x from previous iteration's readers
        if (threadIdx.x < 16)
            s_row[threadIdx.x] = (t0 + threadIdx.x < m)
                                 ? g_list[layer][base + t0 + threadIdx.x] : -1;

        float2 acc[4][NP];
        #pragma unroll
        for (int j = 0; j < 4; j++)
            #pragma unroll
            for (int p = 0; p < NP; p++) acc[j][p] = make_float2(0.f, 0.f);

        for (int kc = 0; kc < KLEN; kc += 512) {
            __syncthreads();
            // stage 16 x 512 chunk of X (float4, coalesced)
            for (int i = threadIdx.x; i < 16 * 128; i += 128) {
                int t = i >> 7, k4 = i & 127;
                int r = s_row[t];
                float4 v = (r >= 0)
                    ? *(const float4*)(X + (size_t)r * DIN + k0 + kc + k4 * 4)
                    : make_float4(0.f, 0.f, 0.f, 0.f);
                *(float4*)&s_x[t][k4 * 4] = v;
            }
            __syncthreads();

            const float* wp = Wb + (size_t)(k0 + kc) * DOUT;
            #pragma unroll 1
            for (int k = 0; k < 512; k += 8) {
                // batch 8 independent W row loads (MLP = 8 per lane)
                float2 w[8][NP];
                #pragma unroll
                for (int u = 0; u < 8; u++) {
                    if (CPT == 4) {
                        float4 w4 = *(const float4*)(wp + (size_t)(k + u) * DOUT);
                        w[u][0] = make_float2(w4.x, w4.y);
                        w[u][NP - 1] = make_float2(w4.z, w4.w);
                    } else {
                        w[u][0] = *(const float2*)(wp + (size_t)(k + u) * DOUT);
                    }
                }
                // 8 x values per token via two LDS.128
                float xs[4][8];
                #pragma unroll
                for (int j = 0; j < 4; j++) {
                    float4 xa = *(const float4*)&s_x[wg * 4 + j][k];
                    float4 xb = *(const float4*)&s_x[wg * 4 + j][k + 4];
                    xs[j][0] = xa.x; xs[j][1] = xa.y; xs[j][2] = xa.z; xs[j][3] = xa.w;
                    xs[j][4] = xb.x; xs[j][5] = xb.y; xs[j][6] = xb.z; xs[j][7] = xb.w;
                }
                #pragma unroll
                for (int u = 0; u < 8; u++)
                    #pragma unroll
                    for (int j = 0; j < 4; j++) {
                        float2 xx = make_float2(xs[j][u], xs[j][u]);
                        #pragma unroll
                        for (int p = 0; p < NP; p++)
                            acc[j][p] = ffma2(xx, w[u][p], acc[j][p]);
                    }
            }
        }

        // epilogue
        #pragma unroll
        for (int j = 0; j < 4; j++) {
            int r = s_row[wg * 4 + j];
            if (r < 0) continue;
            if (EPI) {
                float g = gatep[r];
                float ov[CPT];
                #pragma unroll
                for (int p = 0; p < NP; p++) {
                    float v0 = (acc[j][p].x + bl[2 * p])     * g;
                    float v1 = (acc[j][p].y + bl[2 * p + 1]) * g;
                    if (GELU) { v0 = gelu_f(v0); v1 = gelu_f(v1); }
                    ov[2 * p] = v0; ov[2 * p + 1] = v1;
                }
                float* op = OUT + (size_t)r * DOUT + colBase;
                if (CPT == 4)
                    *(float4*)op = make_float4(ov[0], ov[1], ov[2], ov[3]);
                else
                    *(float2*)op = make_float2(ov[0], ov[1]);
            } else {
                // raw partial sums (bias/gate applied in epilogue kernel)
                float* op = OUT + ((size_t)blockIdx.z * NTOK + r) * DOUT + colBase;
                if (CPT == 4)
                    *(float4*)op = make_float4(acc[j][0].x, acc[j][0].y,
                                               acc[j][NP - 1].x, acc[j][NP - 1].y);
                else
                    *(float2*)op = acc[j][0];
            }
        }
    }
}

// ---------------- FC2 K-split combine + bias + gate --------------------------
// grid = NTOK blocks, 128 threads; each thread does one float4 (512 cols)
__global__ void epi2_kernel(const float* __restrict__ B2v,
                            float* __restrict__ OUT) {
    const int t = blockIdx.x;
    const int c = threadIdx.x * 4;
    const int e = g_idx[1][t];
    const float g = g_gate[1][t];
    float4 p0 = *(const float4*)&g_part[(size_t)t * DIMV + c];
    float4 p1 = *(const float4*)&g_part[(size_t)(NTOK + t) * DIMV + c];
    float4 b  = *(const float4*)(B2v + (size_t)e * DIMV + c);
    float4 o;
    o.x = (p0.x + p1.x + b.x) * g;
    o.y = (p0.y + p1.y + b.y) * g;
    o.z = (p0.z + p1.z + b.z) * g;
    o.w = (p0.w + p1.w + b.w) * g;
    *(float4*)(OUT + (size_t)t * DIMV + c) = o;
}

// ---------------- launch ------------------------------------------------------
extern "C" void kernel_launch(void* const* d_in, const int* in_sizes, int n_in,
                              void* d_out, int out_size) {
    const float* x    = (const float*)d_in[0];
    const float* emb1 = (const float*)d_in[1];
    const float* W1   = (const float*)d_in[2];
    const float* b1   = (const float*)d_in[3];
    const float* emb2 = (const float*)d_in[4];
    const float* W2   = (const float*)d_in[5];
    const float* b2   = (const float*)d_in[6];
    float* out = (float*)d_out;

    void* hp = nullptr;
    cudaGetSymbolAddress(&hp, g_h);
    float* h = (float*)hp;
    void* pp = nullptr;
    cudaGetSymbolAddress(&pp, g_part);
    float* part = (float*)pp;

    const float scale1 = 0.044194173824159216f;   // 1/sqrt(512)
    const float scale2 = 0.022097086912079612f;   // 1/sqrt(2048)

    zero_kernel<<<1, 64>>>();

    gating_kernel<<<NTOK, 64>>>(x, emb1, DIMV, scale1, 0);
    group_kernel<<<1, 256>>>(0);
    // FC1: full K in one pass, fused epilogue (gelu)
    fc_kernel<DIMV, HIDV, 4, 512, true, true>
        <<<dim3(HIDV / 128, NEXP, 1), 128>>>(x, W1, b1, 0, h);

    gating_kernel<<<NTOK, 64>>>(h, emb2, HIDV, scale2, 1);
    group_kernel<<<1, 256>>>(1);
    // FC2: K split in 2 (grid.z), partial sums to g_part, then combine
    fc_kernel<HIDV, DIMV, 2, 1024, false, false>
        <<<dim3(DIMV / 64, NEXP, 2), 128>>>(h, W2, b2, 1, part);
    epi2_kernel<<<NTOK, 128>>>(b2, out);
}